// round 2
// baseline (speedup 1.0000x reference)
#include <cuda_runtime.h>
#include <stdint.h>

// PatchNCELoss: loss[r] = logsumexp_c( inv_t * q[r]·k[c] ) - inv_t * q[r]·k[r]
// Q,K: [8192, 256] fp32 (flattened [32,256,256]).

#define N_TOT 8192
#define DDIM  256
#define TM    64
#define TN    64
#define TK    16
#define COLSPLIT 8
#define COLS_PER_BLK (N_TOT / COLSPLIT)   // 1024
#define NTILES (COLS_PER_BLK / TN)        // 16

__device__ float g_pmax[N_TOT * COLSPLIT];
__device__ float g_psum[N_TOT * COLSPLIT];

__device__ __forceinline__ float neg_inf() { return __int_as_float(0xff800000); }

__device__ __forceinline__ unsigned long long pack2(float a, float b) {
    unsigned long long r;
    asm("mov.b64 %0, {%1, %2};" : "=l"(r) : "f"(a), "f"(b));
    return r;
}
__device__ __forceinline__ void unpack2(unsigned long long v, float& a, float& b) {
    asm("mov.b64 {%0, %1}, %2;" : "=f"(a), "=f"(b) : "l"(v));
}
// packed fp32x2 FMA (sm_100+): d = a*b + d
__device__ __forceinline__ void fma2(unsigned long long& d, unsigned long long a,
                                     unsigned long long b) {
    asm("fma.rn.f32x2 %0, %1, %2, %0;" : "+l"(d) : "l"(a), "l"(b));
}

// ---------------------------------------------------------------------------
// Kernel 1: tiled GEMM (TM x TN micro-tiles, D=256 reduction) fused with
// online (max, sum-exp) per row, per column-split. grid = (COLSPLIT, N/TM).
// ---------------------------------------------------------------------------
__global__ void __launch_bounds__(256)
gemm_lse_kernel(const float* __restrict__ Q, const float* __restrict__ K) {
    __shared__ float Qs[TK][TM];   // transposed: Qs[kk][row], scaled by inv_t
    __shared__ float Ks[TK][TN];   // transposed: Ks[kk][col]

    const float INV_T = 14.2857142857142857f;  // 1/0.07

    const int tid = threadIdx.x;
    const int tx = tid & 15;        // column micro-tile index (0..15)
    const int ty = tid >> 4;        // row micro-tile index    (0..15)
    const int rowBase = blockIdx.y * TM;
    const int colBase = blockIdx.x * COLS_PER_BLK;

    // load assignment: thread -> (row lr, k-group kg), coalesced 64B per 4 lanes
    const int lr = tid >> 2;        // 0..63
    const int kgp = tid & 3;        // 0..3 -> 4 floats each

    float m[4], s[4];
#pragma unroll
    for (int i = 0; i < 4; i++) { m[i] = neg_inf(); s[i] = 0.f; }

    const float* qg = Q + (size_t)(rowBase + lr) * DDIM + kgp * 4;

    for (int ct = 0; ct < NTILES; ct++) {
        unsigned long long acc[4][2];
#pragma unroll
        for (int i = 0; i < 4; i++) { acc[i][0] = 0ull; acc[i][1] = 0ull; }

        const float* kgm = K + (size_t)(colBase + ct * TN + lr) * DDIM + kgp * 4;

        for (int kb = 0; kb < DDIM; kb += TK) {
            float4 qv = *(const float4*)(qg + kb);
            float4 kv = *(const float4*)(kgm + kb);
            __syncthreads();   // previous tile's smem fully consumed
            // scale Q by inv_t once here (saves epilogue muls)
            Qs[kgp * 4 + 0][lr] = qv.x * INV_T;
            Qs[kgp * 4 + 1][lr] = qv.y * INV_T;
            Qs[kgp * 4 + 2][lr] = qv.z * INV_T;
            Qs[kgp * 4 + 3][lr] = qv.w * INV_T;
            Ks[kgp * 4 + 0][lr] = kv.x;
            Ks[kgp * 4 + 1][lr] = kv.y;
            Ks[kgp * 4 + 2][lr] = kv.z;
            Ks[kgp * 4 + 3][lr] = kv.w;
            __syncthreads();

#pragma unroll
            for (int kk = 0; kk < TK; kk++) {
                const float4 q4 = *(const float4*)&Qs[kk][ty * 4];
                const ulonglong2 k2 = *(const ulonglong2*)&Ks[kk][tx * 4];
                unsigned long long qq0 = pack2(q4.x, q4.x);
                unsigned long long qq1 = pack2(q4.y, q4.y);
                unsigned long long qq2 = pack2(q4.z, q4.z);
                unsigned long long qq3 = pack2(q4.w, q4.w);
                fma2(acc[0][0], qq0, k2.x); fma2(acc[0][1], qq0, k2.y);
                fma2(acc[1][0], qq1, k2.x); fma2(acc[1][1], qq1, k2.y);
                fma2(acc[2][0], qq2, k2.x); fma2(acc[2][1], qq2, k2.y);
                fma2(acc[3][0], qq3, k2.x); fma2(acc[3][1], qq3, k2.y);
            }
        }

        // epilogue: online logsumexp update over this 64-col tile
#pragma unroll
        for (int i = 0; i < 4; i++) {
            float c0, c1, c2, c3;
            unpack2(acc[i][0], c0, c1);
            unpack2(acc[i][1], c2, c3);
            float lm = fmaxf(fmaxf(c0, c1), fmaxf(c2, c3));
            // reduce over the 16 threads sharing this row group (lane bits 0..3)
#pragma unroll
            for (int o = 8; o > 0; o >>= 1)
                lm = fmaxf(lm, __shfl_xor_sync(0xffffffffu, lm, o));
            float nm = fmaxf(m[i], lm);
            float ls = __expf(c0 - nm) + __expf(c1 - nm) +
                       __expf(c2 - nm) + __expf(c3 - nm);
#pragma unroll
            for (int o = 8; o > 0; o >>= 1)
                ls += __shfl_xor_sync(0xffffffffu, ls, o);
            s[i] = s[i] * __expf(m[i] - nm) + ls;
            m[i] = nm;
        }
    }

    if (tx == 0) {
#pragma unroll
        for (int i = 0; i < 4; i++) {
            int r = rowBase + ty * 4 + i;
            g_pmax[r * COLSPLIT + blockIdx.x] = m[i];
            g_psum[r * COLSPLIT + blockIdx.x] = s[i];
        }
    }
}

// ---------------------------------------------------------------------------
// Kernel 2: combine the COLSPLIT partials + diagonal dot. One warp per row.
// ---------------------------------------------------------------------------
__global__ void __launch_bounds__(256)
combine_kernel(const float* __restrict__ Q, const float* __restrict__ K,
               float* __restrict__ out) {
    const float INV_T = 14.2857142857142857f;
    int gwarp = (blockIdx.x * blockDim.x + threadIdx.x) >> 5;
    int lane = threadIdx.x & 31;
    if (gwarp >= N_TOT) return;

    const float4* q4 = (const float4*)(Q + (size_t)gwarp * DDIM);
    const float4* k4 = (const float4*)(K + (size_t)gwarp * DDIM);
    float dot = 0.f;
#pragma unroll
    for (int it = 0; it < DDIM / 4 / 32; it++) {
        int idx = it * 32 + lane;
        float4 a = q4[idx];
        float4 b = k4[idx];
        dot += a.x * b.x + a.y * b.y + a.z * b.z + a.w * b.w;
    }
#pragma unroll
    for (int o = 16; o > 0; o >>= 1)
        dot += __shfl_xor_sync(0xffffffffu, dot, o);

    if (lane == 0) {
        float M = neg_inf();
#pragma unroll
        for (int j = 0; j < COLSPLIT; j++)
            M = fmaxf(M, g_pmax[gwarp * COLSPLIT + j]);
        float S = 0.f;
#pragma unroll
        for (int j = 0; j < COLSPLIT; j++)
            S += g_psum[gwarp * COLSPLIT + j] *
                 __expf(g_pmax[gwarp * COLSPLIT + j] - M);
        out[gwarp] = M + logf(S) - dot * INV_T;
    }
}

extern "C" void kernel_launch(void* const* d_in, const int* in_sizes, int n_in,
                              void* d_out, int out_size) {
    const float* Q = (const float*)d_in[0];
    const float* K = (const float*)d_in[1];
    float* out = (float*)d_out;

    dim3 grid1(COLSPLIT, N_TOT / TM);   // (8, 128)
    gemm_lse_kernel<<<grid1, 256>>>(Q, K);

    int warps = N_TOT;
    int threads = 256;
    int blocks = (warps * 32 + threads - 1) / threads;  // 1024
    combine_kernel<<<blocks, threads>>>(Q, K, out);
}

// round 4
// speedup vs baseline: 3.0785x; 3.0785x over previous
#include <cuda_runtime.h>
#include <cuda_bf16.h>
#include <stdint.h>

// =====================================================================
// PatchNCELoss: loss[r] = lse_c( inv_t * q[r]·k[c] ) - inv_t * q[r]·k[r]
// Q,K: [8192, 256] fp32.  bf16 hi/lo split -> 3 GEMM products fused into
// one K=768 mma.sync mainloop + online log2-domain softmax.
// (tcgen05 PTX rejected by harness target compute_103 -> mma.sync path.)
// =====================================================================

#define N_TOT 8192
#define DDIM  256
#define INV_T_F     14.285714285714286f
#define QSCALE_F    20.609929155556627f   /* inv_t * log2(e) */
#define LN2_F       0.6931471805599453f

#define C_SPLIT   2
#define COLS_PER  (N_TOT / C_SPLIT)        // 4096
#define NTILES    (COLS_PER / 128)         // 32
#define CHUNKS_PT 12                       // 3 segments x 4 k64-chunks
#define TOT_CHUNK (NTILES * CHUNKS_PT)     // 384

// ---- device scratch ----
__device__ __align__(256) __nv_bfloat16 g_Qh[N_TOT * DDIM];
__device__ __align__(256) __nv_bfloat16 g_Ql[N_TOT * DDIM];
__device__ __align__(256) __nv_bfloat16 g_Kh[N_TOT * DDIM];
__device__ __align__(256) __nv_bfloat16 g_Kl[N_TOT * DDIM];
__device__ float g_diag[N_TOT];
__device__ float g_m[N_TOT * 4];
__device__ float g_s[N_TOT * 4];

// ---------------- PTX helpers (all legal on compute_103) ----------------
__device__ __forceinline__ uint32_t smem_u32(const void* p) {
    uint32_t a;
    asm("{ .reg .u64 t; cvta.to.shared.u64 t, %1; cvt.u32.u64 %0, t; }"
        : "=r"(a) : "l"(p));
    return a;
}
__device__ __forceinline__ void cp16(uint32_t dst, const void* src) {
    asm volatile("cp.async.cg.shared.global [%0], [%1], 16;"
                 :: "r"(dst), "l"(src) : "memory");
}
__device__ __forceinline__ void cp_commit() {
    asm volatile("cp.async.commit_group;" ::: "memory");
}
template <int N>
__device__ __forceinline__ void cp_wait() {
    asm volatile("cp.async.wait_group %0;" :: "n"(N) : "memory");
}
__device__ __forceinline__ void ldsm4(uint32_t* r, uint32_t addr) {
    asm volatile("ldmatrix.sync.aligned.m8n8.x4.shared.b16 {%0,%1,%2,%3}, [%4];"
                 : "=r"(r[0]), "=r"(r[1]), "=r"(r[2]), "=r"(r[3]) : "r"(addr));
}
__device__ __forceinline__ void mma16816(float* d, const uint32_t* a, const uint32_t* b) {
    asm volatile(
        "mma.sync.aligned.m16n8k16.row.col.f32.bf16.bf16.f32 "
        "{%0,%1,%2,%3}, {%4,%5,%6,%7}, {%8,%9}, {%0,%1,%2,%3};"
        : "+f"(d[0]), "+f"(d[1]), "+f"(d[2]), "+f"(d[3])
        : "r"(a[0]), "r"(a[1]), "r"(a[2]), "r"(a[3]), "r"(b[0]), "r"(b[1]));
}
__device__ __forceinline__ float ex2f(float x) {
    float y;
    asm("ex2.approx.ftz.f32 %0, %1;" : "=f"(y) : "f"(x));
    return y;
}

// ---------------------------------------------------------------------
// Kernel 1: prep — bf16 hi/lo split (Q scaled by inv_t*log2e) + exact
// fp32 diagonal dot. One block (64 threads) per row.
// ---------------------------------------------------------------------
__global__ void __launch_bounds__(64)
prep_kernel(const float* __restrict__ Q, const float* __restrict__ K) {
    const int row = blockIdx.x;
    const int lt = threadIdx.x;           // 0..63, 4 elems each
    __shared__ float red[2];

    float4 q4 = ((const float4*)(Q + (size_t)row * DDIM))[lt];
    float4 k4 = ((const float4*)(K + (size_t)row * DDIM))[lt];

    float dot = q4.x * k4.x + q4.y * k4.y + q4.z * k4.z + q4.w * k4.w;

    float qs[4] = {q4.x * QSCALE_F, q4.y * QSCALE_F, q4.z * QSCALE_F, q4.w * QSCALE_F};
    float kv[4] = {k4.x, k4.y, k4.z, k4.w};
    __nv_bfloat16 qh[4], ql[4], kh[4], kl[4];
#pragma unroll
    for (int i = 0; i < 4; i++) {
        qh[i] = __float2bfloat16(qs[i]);
        ql[i] = __float2bfloat16(qs[i] - __bfloat162float(qh[i]));
        kh[i] = __float2bfloat16(kv[i]);
        kl[i] = __float2bfloat16(kv[i] - __bfloat162float(kh[i]));
    }
    size_t b2 = (size_t)row * (DDIM / 2) + lt * 2;
    ((__nv_bfloat162*)g_Qh)[b2]     = __halves2bfloat162(qh[0], qh[1]);
    ((__nv_bfloat162*)g_Qh)[b2 + 1] = __halves2bfloat162(qh[2], qh[3]);
    ((__nv_bfloat162*)g_Ql)[b2]     = __halves2bfloat162(ql[0], ql[1]);
    ((__nv_bfloat162*)g_Ql)[b2 + 1] = __halves2bfloat162(ql[2], ql[3]);
    ((__nv_bfloat162*)g_Kh)[b2]     = __halves2bfloat162(kh[0], kh[1]);
    ((__nv_bfloat162*)g_Kh)[b2 + 1] = __halves2bfloat162(kh[2], kh[3]);
    ((__nv_bfloat162*)g_Kl)[b2]     = __halves2bfloat162(kl[0], kl[1]);
    ((__nv_bfloat162*)g_Kl)[b2 + 1] = __halves2bfloat162(kl[2], kl[3]);

#pragma unroll
    for (int o = 16; o > 0; o >>= 1)
        dot += __shfl_xor_sync(0xffffffffu, dot, o);
    if ((lt & 31) == 0) red[lt >> 5] = dot;
    __syncthreads();
    if (lt == 0) g_diag[row] = red[0] + red[1];
}

// ---------------------------------------------------------------------
// Kernel 2: mma.sync bf16 GEMM + online log2-softmax.
// grid (C_SPLIT, 64). 256 threads = 8 warps (4 along M x 2 along N).
// CTA tile: 128 rows x 128 cols per N-tile, K=768 virtual
// (seg0 Qh*Kh, seg1 Qh*Kl, seg2 Ql*Kh), 32 N-tiles per CTA.
// SMEM: A = Qh|Ql [128x256] resident (128KB), B 3-stage ring (3x16KB).
// ---------------------------------------------------------------------
#define A_BYTES   (2 * 128 * 512)          // 131072
#define B_STAGE   (128 * 128)              // 16384
#define SMEM_DYN  (1024 + A_BYTES + 3 * B_STAGE)

__global__ void __launch_bounds__(256, 1)
gemm_lse_kernel() {
    extern __shared__ char dsm[];
    const uint32_t base = (smem_u32(dsm) + 127u) & ~127u;
    const uint32_t A0 = base;                    // Qh [128][256], then Ql
    const uint32_t B0 = base + A_BYTES;          // 3 stages

    const int tid = threadIdx.x;
    const int wid = tid >> 5, lane = tid & 31;
    const int warp_m = wid & 3;                  // 0..3 (rows of 32)
    const int warp_n = wid >> 2;                 // 0..1 (cols of 64)
    const int rowBase = blockIdx.y * 128;
    const int colBase = blockIdx.x * COLS_PER;

    // ---- load A (Qh,Ql rows rowBase..+127) into SMEM, swizzled ----
    // layout: byte = half*65536 + row*512 + ((kc ^ (row&7))<<4), kc = k/8
    for (int ii = 0; ii < 32; ii++) {
        int idx = ii * 256 + tid;               // 0..8191 16B-chunks
        int half = idx >> 12;
        int rest = idx & 4095;
        int row = rest >> 5, kc = rest & 31;
        const __nv_bfloat16* src =
            (half ? g_Ql : g_Qh) + (size_t)(rowBase + row) * DDIM + kc * 8;
        cp16(A0 + half * 65536 + row * 512 + (((uint32_t)(kc ^ (row & 7))) << 4), src);
    }
    cp_commit();   // group: A

    // ---- per-thread B load descriptors (4 x 16B per chunk) ----
    int bn[4]; uint32_t bsrcoff[4], bdst[4];
#pragma unroll
    for (int ii = 0; ii < 4; ii++) {
        int idx = ii * 256 + tid;               // 0..1023
        int n = idx >> 3, kc = idx & 7;
        bn[ii] = n;
        bsrcoff[ii] = (uint32_t)(n * DDIM + kc * 8);
        bdst[ii] = (uint32_t)(n * 128 + ((kc ^ (n & 7)) << 4));
    }

    // chunk loader: c -> (ntile, seg, kc4)
    auto loadB = [&](int c) {
        int ntile = c / CHUNKS_PT;
        int sub = c % CHUNKS_PT;
        int seg = sub >> 2, kc4 = sub & 3;      // seg: 0 Kh, 1 Kl, 2 Kh
        const __nv_bfloat16* bsrc = (seg == 1) ? g_Kl : g_Kh;
        const __nv_bfloat16* srow =
            bsrc + (size_t)(colBase + ntile * 128) * DDIM + kc4 * 64;
        uint32_t dstB = B0 + (uint32_t)(c % 3) * B_STAGE;
#pragma unroll
        for (int ii = 0; ii < 4; ii++)
            cp16(dstB + bdst[ii], srow + bsrcoff[ii]);
    };

    loadB(0); cp_commit();
    loadB(1); cp_commit();

    // ---- compute-side address precompute ----
    int rowA[2], rswA[2];
#pragma unroll
    for (int mi = 0; mi < 2; mi++) {
        rowA[mi] = warp_m * 32 + mi * 16 + (lane & 7) + ((lane & 8) ? 8 : 0);
        rswA[mi] = rowA[mi] & 7;
    }
    const int khalf = (lane >> 4) & 1;
    const int hhB = (lane >> 3) & 1;
    uint32_t bOff[4]; int bsw[4];
#pragma unroll
    for (int gp = 0; gp < 4; gp++) {
        int gg = 2 * gp + ((lane >> 4) & 1);
        int nB = warp_n * 64 + gg * 8 + (lane & 7);
        bOff[gp] = (uint32_t)(nB * 128);
        bsw[gp] = nB & 7;
    }

    float acc[2][8][4];
    float m[4], s[4];
#pragma unroll
    for (int j = 0; j < 4; j++) { m[j] = __int_as_float(0xff800000); s[j] = 0.f; }
#pragma unroll
    for (int mi = 0; mi < 2; mi++)
#pragma unroll
        for (int g = 0; g < 8; g++)
#pragma unroll
            for (int v = 0; v < 4; v++) acc[mi][g][v] = 0.f;

    for (int c = 0; c < TOT_CHUNK; c++) {
        cp_wait<1>();          // chunk c resident (A done on first iter too)
        __syncthreads();

        const int sub = c % CHUNKS_PT;
        const int seg = sub >> 2, kc4 = sub & 3;
        const uint32_t Asel = A0 + ((seg == 2) ? 65536u : 0u);
        const uint32_t Bst = B0 + (uint32_t)(c % 3) * B_STAGE;

#pragma unroll
        for (int ks = 0; ks < 4; ks++) {
            const int k0c = (kc4 * 64 + ks * 16) >> 3;   // even
            uint32_t a[2][4];
#pragma unroll
            for (int mi = 0; mi < 2; mi++) {
                uint32_t ch = (uint32_t)(k0c | khalf);
                ldsm4(a[mi], Asel + (uint32_t)rowA[mi] * 512 +
                              (((ch ^ (uint32_t)rswA[mi])) << 4));
            }
            uint32_t b[8][2];
#pragma unroll
            for (int gp = 0; gp < 4; gp++) {
                uint32_t t4[4];
                uint32_t ch = (uint32_t)(ks * 2 + hhB);
                ldsm4(t4, Bst + bOff[gp] + ((ch ^ (uint32_t)bsw[gp]) << 4));
                b[2 * gp][0] = t4[0]; b[2 * gp][1] = t4[1];
                b[2 * gp + 1][0] = t4[2]; b[2 * gp + 1][1] = t4[3];
            }
#pragma unroll
            for (int mi = 0; mi < 2; mi++)
#pragma unroll
                for (int g = 0; g < 8; g++)
                    mma16816(acc[mi][g], a[mi], b[g]);
        }

        __syncthreads();
        if (c + 2 < TOT_CHUNK) loadB(c + 2);
        cp_commit();           // empty group when nothing issued is fine

        if (sub == CHUNKS_PT - 1) {
            // ---- online softmax update for this 128-col tile ----
#pragma unroll
            for (int j = 0; j < 4; j++) {
                const int mi = j >> 1, p = j & 1;
                float rm = acc[mi][0][2 * p];
#pragma unroll
                for (int g = 0; g < 8; g++) {
                    rm = fmaxf(rm, acc[mi][g][2 * p]);
                    rm = fmaxf(rm, acc[mi][g][2 * p + 1]);
                }
                rm = fmaxf(rm, __shfl_xor_sync(0xffffffffu, rm, 1));
                rm = fmaxf(rm, __shfl_xor_sync(0xffffffffu, rm, 2));
                float nm = fmaxf(m[j], rm);
                float ssum = 0.f;
#pragma unroll
                for (int g = 0; g < 8; g++) {
                    ssum += ex2f(acc[mi][g][2 * p] - nm);
                    ssum += ex2f(acc[mi][g][2 * p + 1] - nm);
                }
                ssum += __shfl_xor_sync(0xffffffffu, ssum, 1);
                ssum += __shfl_xor_sync(0xffffffffu, ssum, 2);
                s[j] = s[j] * ex2f(m[j] - nm) + ssum;
                m[j] = nm;
            }
#pragma unroll
            for (int mi = 0; mi < 2; mi++)
#pragma unroll
                for (int g = 0; g < 8; g++)
#pragma unroll
                    for (int v = 0; v < 4; v++) acc[mi][g][v] = 0.f;
        }
    }

    if ((lane & 3) == 0) {
#pragma unroll
        for (int j = 0; j < 4; j++) {
            int row = rowBase + warp_m * 32 + (lane >> 2) + 8 * j;
            int slot = blockIdx.x * 2 + warp_n;
            g_m[row * 4 + slot] = m[j];
            g_s[row * 4 + slot] = s[j];
        }
    }
}

// ---------------------------------------------------------------------
// Kernel 3: combine 4 partials per row into the loss.
// ---------------------------------------------------------------------
__global__ void __launch_bounds__(256)
combine_kernel(float* __restrict__ out) {
    int i = blockIdx.x * blockDim.x + threadIdx.x;
    if (i >= N_TOT) return;
    float M = g_m[4 * i];
#pragma unroll
    for (int j = 1; j < 4; j++) M = fmaxf(M, g_m[4 * i + j]);
    float S = 0.f;
#pragma unroll
    for (int j = 0; j < 4; j++)
        S += g_s[4 * i + j] * ex2f(g_m[4 * i + j] - M);
    out[i] = LN2_F * (M + log2f(S)) - INV_T_F * g_diag[i];
}

// ---------------------------------------------------------------------
extern "C" void kernel_launch(void* const* d_in, const int* in_sizes, int n_in,
                              void* d_out, int out_size) {
    const float* Q = (const float*)d_in[0];
    const float* K = (const float*)d_in[1];
    float* out = (float*)d_out;

    static int attr_set = 0;
    if (!attr_set) {
        cudaFuncSetAttribute(gemm_lse_kernel,
                             cudaFuncAttributeMaxDynamicSharedMemorySize, SMEM_DYN);
        attr_set = 1;
    }

    prep_kernel<<<N_TOT, 64>>>(Q, K);
    dim3 g2(C_SPLIT, 64);
    gemm_lse_kernel<<<g2, 256, SMEM_DYN>>>();
    combine_kernel<<<32, 256>>>(out);
}

// round 5
// speedup vs baseline: 3.1376x; 1.0192x over previous
#include <cuda_runtime.h>
#include <cuda_bf16.h>
#include <stdint.h>

// =====================================================================
// PatchNCELoss: loss[r] = lse_c( inv_t * q[r]·k[c] ) - inv_t * q[r]·k[r]
// Q,K: [8192, 256] fp32.  bf16 hi/lo split -> 3 GEMM products fused into
// one K=768 mma.sync mainloop + online log2-domain softmax.
// R5: 4-stage cp.async ring, prefetch distance 3, one barrier per chunk.
// =====================================================================

#define N_TOT 8192
#define DDIM  256
#define INV_T_F     14.285714285714286f
#define QSCALE_F    20.609929155556627f   /* inv_t * log2(e) */
#define LN2_F       0.6931471805599453f

#define C_SPLIT   2
#define COLS_PER  (N_TOT / C_SPLIT)        // 4096
#define NTILES    (COLS_PER / 128)         // 32
#define CHUNKS_PT 12                       // 3 segments x 4 k64-chunks
#define TOT_CHUNK (NTILES * CHUNKS_PT)     // 384

// ---- device scratch ----
__device__ __align__(256) __nv_bfloat16 g_Qh[N_TOT * DDIM];
__device__ __align__(256) __nv_bfloat16 g_Ql[N_TOT * DDIM];
__device__ __align__(256) __nv_bfloat16 g_Kh[N_TOT * DDIM];
__device__ __align__(256) __nv_bfloat16 g_Kl[N_TOT * DDIM];
__device__ float g_diag[N_TOT];
__device__ float g_m[N_TOT * 4];
__device__ float g_s[N_TOT * 4];

// ---------------- PTX helpers ----------------
__device__ __forceinline__ uint32_t smem_u32(const void* p) {
    uint32_t a;
    asm("{ .reg .u64 t; cvta.to.shared.u64 t, %1; cvt.u32.u64 %0, t; }"
        : "=r"(a) : "l"(p));
    return a;
}
__device__ __forceinline__ void cp16(uint32_t dst, const void* src) {
    asm volatile("cp.async.cg.shared.global [%0], [%1], 16;"
                 :: "r"(dst), "l"(src) : "memory");
}
__device__ __forceinline__ void cp_commit() {
    asm volatile("cp.async.commit_group;" ::: "memory");
}
template <int N>
__device__ __forceinline__ void cp_wait() {
    asm volatile("cp.async.wait_group %0;" :: "n"(N) : "memory");
}
__device__ __forceinline__ void ldsm4(uint32_t* r, uint32_t addr) {
    asm volatile("ldmatrix.sync.aligned.m8n8.x4.shared.b16 {%0,%1,%2,%3}, [%4];"
                 : "=r"(r[0]), "=r"(r[1]), "=r"(r[2]), "=r"(r[3]) : "r"(addr));
}
__device__ __forceinline__ void mma16816(float* d, const uint32_t* a, const uint32_t* b) {
    asm volatile(
        "mma.sync.aligned.m16n8k16.row.col.f32.bf16.bf16.f32 "
        "{%0,%1,%2,%3}, {%4,%5,%6,%7}, {%8,%9}, {%0,%1,%2,%3};"
        : "+f"(d[0]), "+f"(d[1]), "+f"(d[2]), "+f"(d[3])
        : "r"(a[0]), "r"(a[1]), "r"(a[2]), "r"(a[3]), "r"(b[0]), "r"(b[1]));
}
__device__ __forceinline__ float ex2f(float x) {
    float y;
    asm("ex2.approx.ftz.f32 %0, %1;" : "=f"(y) : "f"(x));
    return y;
}

// ---------------------------------------------------------------------
// Kernel 1: prep — bf16 hi/lo split (Q scaled by inv_t*log2e) + exact
// fp32 diagonal dot. One block (64 threads) per row.
// ---------------------------------------------------------------------
__global__ void __launch_bounds__(64)
prep_kernel(const float* __restrict__ Q, const float* __restrict__ K) {
    const int row = blockIdx.x;
    const int lt = threadIdx.x;           // 0..63, 4 elems each
    __shared__ float red[2];

    float4 q4 = ((const float4*)(Q + (size_t)row * DDIM))[lt];
    float4 k4 = ((const float4*)(K + (size_t)row * DDIM))[lt];

    float dot = q4.x * k4.x + q4.y * k4.y + q4.z * k4.z + q4.w * k4.w;

    float qs[4] = {q4.x * QSCALE_F, q4.y * QSCALE_F, q4.z * QSCALE_F, q4.w * QSCALE_F};
    float kv[4] = {k4.x, k4.y, k4.z, k4.w};
    __nv_bfloat16 qh[4], ql[4], kh[4], kl[4];
#pragma unroll
    for (int i = 0; i < 4; i++) {
        qh[i] = __float2bfloat16(qs[i]);
        ql[i] = __float2bfloat16(qs[i] - __bfloat162float(qh[i]));
        kh[i] = __float2bfloat16(kv[i]);
        kl[i] = __float2bfloat16(kv[i] - __bfloat162float(kh[i]));
    }
    size_t b2 = (size_t)row * (DDIM / 2) + lt * 2;
    ((__nv_bfloat162*)g_Qh)[b2]     = __halves2bfloat162(qh[0], qh[1]);
    ((__nv_bfloat162*)g_Qh)[b2 + 1] = __halves2bfloat162(qh[2], qh[3]);
    ((__nv_bfloat162*)g_Ql)[b2]     = __halves2bfloat162(ql[0], ql[1]);
    ((__nv_bfloat162*)g_Ql)[b2 + 1] = __halves2bfloat162(ql[2], ql[3]);
    ((__nv_bfloat162*)g_Kh)[b2]     = __halves2bfloat162(kh[0], kh[1]);
    ((__nv_bfloat162*)g_Kh)[b2 + 1] = __halves2bfloat162(kh[2], kh[3]);
    ((__nv_bfloat162*)g_Kl)[b2]     = __halves2bfloat162(kl[0], kl[1]);
    ((__nv_bfloat162*)g_Kl)[b2 + 1] = __halves2bfloat162(kl[2], kl[3]);

#pragma unroll
    for (int o = 16; o > 0; o >>= 1)
        dot += __shfl_xor_sync(0xffffffffu, dot, o);
    if ((lt & 31) == 0) red[lt >> 5] = dot;
    __syncthreads();
    if (lt == 0) g_diag[row] = red[0] + red[1];
}

// ---------------------------------------------------------------------
// Kernel 2: mma.sync bf16 GEMM + online log2-softmax.
// grid (C_SPLIT, 64). 256 threads = 8 warps (4 along M x 2 along N).
// SMEM: A = Qh|Ql [128x256] resident (128KB), B 4-stage ring (4x16KB).
// ---------------------------------------------------------------------
#define NSTAGE    4
#define A_BYTES   (2 * 128 * 512)          // 131072
#define B_STAGE   (128 * 128)              // 16384
#define SMEM_DYN  (1024 + A_BYTES + NSTAGE * B_STAGE)

__global__ void __launch_bounds__(256, 1)
gemm_lse_kernel() {
    extern __shared__ char dsm[];
    const uint32_t base = (smem_u32(dsm) + 127u) & ~127u;
    const uint32_t A0 = base;                    // Qh [128][256], then Ql
    const uint32_t B0 = base + A_BYTES;          // NSTAGE stages

    const int tid = threadIdx.x;
    const int wid = tid >> 5, lane = tid & 31;
    const int warp_m = wid & 3;                  // 0..3 (rows of 32)
    const int warp_n = wid >> 2;                 // 0..1 (cols of 64)
    const int rowBase = blockIdx.y * 128;
    const int colBase = blockIdx.x * COLS_PER;

    // ---- load A (Qh,Ql rows rowBase..+127) into SMEM, swizzled ----
    for (int ii = 0; ii < 32; ii++) {
        int idx = ii * 256 + tid;               // 0..8191 16B-chunks
        int half = idx >> 12;
        int rest = idx & 4095;
        int row = rest >> 5, kc = rest & 31;
        const __nv_bfloat16* src =
            (half ? g_Ql : g_Qh) + (size_t)(rowBase + row) * DDIM + kc * 8;
        cp16(A0 + half * 65536 + row * 512 + (((uint32_t)(kc ^ (row & 7))) << 4), src);
    }
    cp_commit();   // group: A

    // ---- per-thread B load descriptors (4 x 16B per chunk) ----
    uint32_t bsrcoff[4], bdst[4];
#pragma unroll
    for (int ii = 0; ii < 4; ii++) {
        int idx = ii * 256 + tid;               // 0..1023
        int n = idx >> 3, kc = idx & 7;
        bsrcoff[ii] = (uint32_t)(n * DDIM + kc * 8);
        bdst[ii] = (uint32_t)(n * 128 + ((kc ^ (n & 7)) << 4));
    }

    // chunk loader: c -> (ntile, seg, kc4)
    auto loadB = [&](int c) {
        int ntile = c / CHUNKS_PT;
        int sub = c % CHUNKS_PT;
        int seg = sub >> 2, kc4 = sub & 3;      // seg: 0 Kh, 1 Kl, 2 Kh
        const __nv_bfloat16* bsrc = (seg == 1) ? g_Kl : g_Kh;
        const __nv_bfloat16* srow =
            bsrc + (size_t)(colBase + ntile * 128) * DDIM + kc4 * 64;
        uint32_t dstB = B0 + (uint32_t)(c & (NSTAGE - 1)) * B_STAGE;
#pragma unroll
        for (int ii = 0; ii < 4; ii++)
            cp16(dstB + bdst[ii], srow + bsrcoff[ii]);
    };

    loadB(0); cp_commit();
    loadB(1); cp_commit();
    loadB(2); cp_commit();

    // ---- compute-side address precompute ----
    int rowA[2], rswA[2];
#pragma unroll
    for (int mi = 0; mi < 2; mi++) {
        rowA[mi] = warp_m * 32 + mi * 16 + (lane & 7) + ((lane & 8) ? 8 : 0);
        rswA[mi] = rowA[mi] & 7;
    }
    const int khalf = (lane >> 4) & 1;
    const int hhB = (lane >> 3) & 1;
    uint32_t bOff[4]; int bsw[4];
#pragma unroll
    for (int gp = 0; gp < 4; gp++) {
        int gg = 2 * gp + ((lane >> 4) & 1);
        int nB = warp_n * 64 + gg * 8 + (lane & 7);
        bOff[gp] = (uint32_t)(nB * 128);
        bsw[gp] = nB & 7;
    }

    float acc[2][8][4];
    float m[4], s[4];
#pragma unroll
    for (int j = 0; j < 4; j++) { m[j] = __int_as_float(0xff800000); s[j] = 0.f; }
#pragma unroll
    for (int mi = 0; mi < 2; mi++)
#pragma unroll
        for (int g = 0; g < 8; g++)
#pragma unroll
            for (int v = 0; v < 4; v++) acc[mi][g][v] = 0.f;

    for (int c = 0; c < TOT_CHUNK; c++) {
        // stage c resident: A + B(c..c+2) in flight max; keep newest 2 pending
        cp_wait<2>();
        __syncthreads();

        // prefetch distance 3 into stage (c+3)&3 == (c-1)&3 (freed by barrier)
        if (c + 3 < TOT_CHUNK) loadB(c + 3);
        cp_commit();

        const int sub = c % CHUNKS_PT;
        const int seg = sub >> 2, kc4 = sub & 3;
        const uint32_t Asel = A0 + ((seg == 2) ? 65536u : 0u);
        const uint32_t Bst = B0 + (uint32_t)(c & (NSTAGE - 1)) * B_STAGE;

#pragma unroll
        for (int ks = 0; ks < 4; ks++) {
            const int k0c = (kc4 * 64 + ks * 16) >> 3;   // even
            uint32_t a[2][4];
#pragma unroll
            for (int mi = 0; mi < 2; mi++) {
                uint32_t ch = (uint32_t)(k0c | khalf);
                ldsm4(a[mi], Asel + (uint32_t)rowA[mi] * 512 +
                              (((ch ^ (uint32_t)rswA[mi])) << 4));
            }
            uint32_t b[8][2];
#pragma unroll
            for (int gp = 0; gp < 4; gp++) {
                uint32_t t4[4];
                uint32_t ch = (uint32_t)(ks * 2 + hhB);
                ldsm4(t4, Bst + bOff[gp] + ((ch ^ (uint32_t)bsw[gp]) << 4));
                b[2 * gp][0] = t4[0]; b[2 * gp][1] = t4[1];
                b[2 * gp + 1][0] = t4[2]; b[2 * gp + 1][1] = t4[3];
            }
#pragma unroll
            for (int mi = 0; mi < 2; mi++)
#pragma unroll
                for (int g = 0; g < 8; g++)
                    mma16816(acc[mi][g], a[mi], b[g]);
        }

        if (sub == CHUNKS_PT - 1) {
            // ---- online softmax update for this 128-col tile ----
#pragma unroll
            for (int j = 0; j < 4; j++) {
                const int mi = j >> 1, p = j & 1;
                float rm = acc[mi][0][2 * p];
#pragma unroll
                for (int g = 0; g < 8; g++) {
                    rm = fmaxf(rm, acc[mi][g][2 * p]);
                    rm = fmaxf(rm, acc[mi][g][2 * p + 1]);
                }
                rm = fmaxf(rm, __shfl_xor_sync(0xffffffffu, rm, 1));
                rm = fmaxf(rm, __shfl_xor_sync(0xffffffffu, rm, 2));
                float nm = fmaxf(m[j], rm);
                float ssum = 0.f;
#pragma unroll
                for (int g = 0; g < 8; g++) {
                    ssum += ex2f(acc[mi][g][2 * p] - nm);
                    ssum += ex2f(acc[mi][g][2 * p + 1] - nm);
                }
                ssum += __shfl_xor_sync(0xffffffffu, ssum, 1);
                ssum += __shfl_xor_sync(0xffffffffu, ssum, 2);
                s[j] = s[j] * ex2f(m[j] - nm) + ssum;
                m[j] = nm;
            }
#pragma unroll
            for (int mi = 0; mi < 2; mi++)
#pragma unroll
                for (int g = 0; g < 8; g++)
#pragma unroll
                    for (int v = 0; v < 4; v++) acc[mi][g][v] = 0.f;
        }
    }

    if ((lane & 3) == 0) {
#pragma unroll
        for (int j = 0; j < 4; j++) {
            int row = rowBase + warp_m * 32 + (lane >> 2) + 8 * j;
            int slot = blockIdx.x * 2 + warp_n;
            g_m[row * 4 + slot] = m[j];
            g_s[row * 4 + slot] = s[j];
        }
    }
}

// ---------------------------------------------------------------------
// Kernel 3: combine 4 partials per row into the loss.
// ---------------------------------------------------------------------
__global__ void __launch_bounds__(256)
combine_kernel(float* __restrict__ out) {
    int i = blockIdx.x * blockDim.x + threadIdx.x;
    if (i >= N_TOT) return;
    float M = g_m[4 * i];
#pragma unroll
    for (int j = 1; j < 4; j++) M = fmaxf(M, g_m[4 * i + j]);
    float S = 0.f;
#pragma unroll
    for (int j = 0; j < 4; j++)
        S += g_s[4 * i + j] * ex2f(g_m[4 * i + j] - M);
    out[i] = LN2_F * (M + log2f(S)) - INV_T_F * g_diag[i];
}

// ---------------------------------------------------------------------
extern "C" void kernel_launch(void* const* d_in, const int* in_sizes, int n_in,
                              void* d_out, int out_size) {
    const float* Q = (const float*)d_in[0];
    const float* K = (const float*)d_in[1];
    float* out = (float*)d_out;

    cudaFuncSetAttribute(gemm_lse_kernel,
                         cudaFuncAttributeMaxDynamicSharedMemorySize, SMEM_DYN);

    prep_kernel<<<N_TOT, 64>>>(Q, K);
    dim3 g2(C_SPLIT, 64);
    gemm_lse_kernel<<<g2, 256, SMEM_DYN>>>();
    combine_kernel<<<32, 256>>>(out);
}

// round 6
// speedup vs baseline: 3.6442x; 1.1615x over previous
#include <cuda_runtime.h>
#include <cuda_bf16.h>
#include <stdint.h>

// =====================================================================
// PatchNCELoss: loss[r] = lse_c( inv_t * q[r]·k[c] ) - inv_t * q[r]·k[r]
// Q,K: [8192, 256] fp32.  bf16 hi/lo split -> 3 GEMM products fused into
// one K=768 mma.sync mainloop + online log2-domain softmax.
// R6: CTA tile 128x256, warp tile 64x64 (2x4 grid) -> 1.5x less LDSM
// traffic per output column; 3-stage 32KB B ring.
// =====================================================================

#define N_TOT 8192
#define DDIM  256
#define INV_T_F     14.285714285714286f
#define QSCALE_F    20.609929155556627f   /* inv_t * log2(e) */
#define LN2_F       0.6931471805599453f

#define C_SPLIT   2
#define COLS_PER  (N_TOT / C_SPLIT)        // 4096
#define NTILES    (COLS_PER / 256)         // 16
#define CHUNKS_PT 12                       // 3 segments x 4 k64-chunks
#define TOT_CHUNK (NTILES * CHUNKS_PT)     // 192
#define NSLOT     8                        // column partials per row

// ---- device scratch ----
__device__ __align__(256) __nv_bfloat16 g_Qh[N_TOT * DDIM];
__device__ __align__(256) __nv_bfloat16 g_Ql[N_TOT * DDIM];
__device__ __align__(256) __nv_bfloat16 g_Kh[N_TOT * DDIM];
__device__ __align__(256) __nv_bfloat16 g_Kl[N_TOT * DDIM];
__device__ float g_diag[N_TOT];
__device__ float g_m[N_TOT * NSLOT];
__device__ float g_s[N_TOT * NSLOT];

// ---------------- PTX helpers ----------------
__device__ __forceinline__ uint32_t smem_u32(const void* p) {
    uint32_t a;
    asm("{ .reg .u64 t; cvta.to.shared.u64 t, %1; cvt.u32.u64 %0, t; }"
        : "=r"(a) : "l"(p));
    return a;
}
__device__ __forceinline__ void cp16(uint32_t dst, const void* src) {
    asm volatile("cp.async.cg.shared.global [%0], [%1], 16;"
                 :: "r"(dst), "l"(src) : "memory");
}
__device__ __forceinline__ void cp_commit() {
    asm volatile("cp.async.commit_group;" ::: "memory");
}
template <int N>
__device__ __forceinline__ void cp_wait() {
    asm volatile("cp.async.wait_group %0;" :: "n"(N) : "memory");
}
__device__ __forceinline__ void ldsm4(uint32_t* r, uint32_t addr) {
    asm volatile("ldmatrix.sync.aligned.m8n8.x4.shared.b16 {%0,%1,%2,%3}, [%4];"
                 : "=r"(r[0]), "=r"(r[1]), "=r"(r[2]), "=r"(r[3]) : "r"(addr));
}
__device__ __forceinline__ void mma16816(float* d, const uint32_t* a, const uint32_t* b) {
    asm volatile(
        "mma.sync.aligned.m16n8k16.row.col.f32.bf16.bf16.f32 "
        "{%0,%1,%2,%3}, {%4,%5,%6,%7}, {%8,%9}, {%0,%1,%2,%3};"
        : "+f"(d[0]), "+f"(d[1]), "+f"(d[2]), "+f"(d[3])
        : "r"(a[0]), "r"(a[1]), "r"(a[2]), "r"(a[3]), "r"(b[0]), "r"(b[1]));
}
__device__ __forceinline__ float ex2f(float x) {
    float y;
    asm("ex2.approx.ftz.f32 %0, %1;" : "=f"(y) : "f"(x));
    return y;
}

// ---------------------------------------------------------------------
// Kernel 1: prep — bf16 hi/lo split (Q scaled by inv_t*log2e) + exact
// fp32 diagonal dot. One block (64 threads) per row.
// ---------------------------------------------------------------------
__global__ void __launch_bounds__(64)
prep_kernel(const float* __restrict__ Q, const float* __restrict__ K) {
    const int row = blockIdx.x;
    const int lt = threadIdx.x;           // 0..63, 4 elems each
    __shared__ float red[2];

    float4 q4 = ((const float4*)(Q + (size_t)row * DDIM))[lt];
    float4 k4 = ((const float4*)(K + (size_t)row * DDIM))[lt];

    float dot = q4.x * k4.x + q4.y * k4.y + q4.z * k4.z + q4.w * k4.w;

    float qs[4] = {q4.x * QSCALE_F, q4.y * QSCALE_F, q4.z * QSCALE_F, q4.w * QSCALE_F};
    float kv[4] = {k4.x, k4.y, k4.z, k4.w};
    __nv_bfloat16 qh[4], ql[4], kh[4], kl[4];
#pragma unroll
    for (int i = 0; i < 4; i++) {
        qh[i] = __float2bfloat16(qs[i]);
        ql[i] = __float2bfloat16(qs[i] - __bfloat162float(qh[i]));
        kh[i] = __float2bfloat16(kv[i]);
        kl[i] = __float2bfloat16(kv[i] - __bfloat162float(kh[i]));
    }
    size_t b2 = (size_t)row * (DDIM / 2) + lt * 2;
    ((__nv_bfloat162*)g_Qh)[b2]     = __halves2bfloat162(qh[0], qh[1]);
    ((__nv_bfloat162*)g_Qh)[b2 + 1] = __halves2bfloat162(qh[2], qh[3]);
    ((__nv_bfloat162*)g_Ql)[b2]     = __halves2bfloat162(ql[0], ql[1]);
    ((__nv_bfloat162*)g_Ql)[b2 + 1] = __halves2bfloat162(ql[2], ql[3]);
    ((__nv_bfloat162*)g_Kh)[b2]     = __halves2bfloat162(kh[0], kh[1]);
    ((__nv_bfloat162*)g_Kh)[b2 + 1] = __halves2bfloat162(kh[2], kh[3]);
    ((__nv_bfloat162*)g_Kl)[b2]     = __halves2bfloat162(kl[0], kl[1]);
    ((__nv_bfloat162*)g_Kl)[b2 + 1] = __halves2bfloat162(kl[2], kl[3]);

#pragma unroll
    for (int o = 16; o > 0; o >>= 1)
        dot += __shfl_xor_sync(0xffffffffu, dot, o);
    if ((lt & 31) == 0) red[lt >> 5] = dot;
    __syncthreads();
    if (lt == 0) g_diag[row] = red[0] + red[1];
}

// ---------------------------------------------------------------------
// Kernel 2: mma.sync bf16 GEMM + online log2-softmax.
// grid (C_SPLIT, 64). 256 threads = 8 warps, grid 2(M)x4(N), 64x64 each.
// SMEM: A = Qh|Ql [128x256] resident (128KB), B 3-stage ring (3x32KB).
// ---------------------------------------------------------------------
#define NSTAGE    3
#define A_BYTES   (2 * 128 * 512)          // 131072
#define B_STAGE   (256 * 128)              // 32768: 256 cols x 64k x 2B
#define SMEM_DYN  (512 + A_BYTES + NSTAGE * B_STAGE)

__global__ void __launch_bounds__(256, 1)
gemm_lse_kernel() {
    extern __shared__ char dsm[];
    const uint32_t base = (smem_u32(dsm) + 127u) & ~127u;
    const uint32_t A0 = base;                    // Qh [128][256], then Ql
    const uint32_t B0 = base + A_BYTES;          // NSTAGE stages

    const int tid = threadIdx.x;
    const int wid = tid >> 5, lane = tid & 31;
    const int warp_m = wid & 1;                  // 0..1 (rows of 64)
    const int warp_n = wid >> 1;                 // 0..3 (cols of 64)
    const int rowBase = blockIdx.y * 128;
    const int colBase = blockIdx.x * COLS_PER;

    // ---- load A (Qh,Ql rows rowBase..+127) into SMEM, swizzled ----
    for (int ii = 0; ii < 32; ii++) {
        int idx = ii * 256 + tid;               // 0..8191 16B-chunks
        int half = idx >> 12;
        int rest = idx & 4095;
        int row = rest >> 5, kc = rest & 31;
        const __nv_bfloat16* src =
            (half ? g_Ql : g_Qh) + (size_t)(rowBase + row) * DDIM + kc * 8;
        cp16(A0 + half * 65536 + row * 512 + (((uint32_t)(kc ^ (row & 7))) << 4), src);
    }
    cp_commit();   // group: A

    // ---- per-thread B load descriptors (8 x 16B per chunk of 256 cols) ----
    uint32_t bsrcoff[8], bdst[8];
#pragma unroll
    for (int ii = 0; ii < 8; ii++) {
        int idx = ii * 256 + tid;               // 0..2047
        int n = idx >> 3, kc = idx & 7;
        bsrcoff[ii] = (uint32_t)(n * DDIM + kc * 8);
        bdst[ii] = (uint32_t)(n * 128 + ((kc ^ (n & 7)) << 4));
    }

    // chunk loader: c -> (ntile, seg, kc4)
    auto loadB = [&](int c) {
        int ntile = c / CHUNKS_PT;
        int sub = c % CHUNKS_PT;
        int seg = sub >> 2, kc4 = sub & 3;      // seg: 0 Kh, 1 Kl, 2 Kh
        const __nv_bfloat16* bsrc = (seg == 1) ? g_Kl : g_Kh;
        const __nv_bfloat16* srow =
            bsrc + (size_t)(colBase + ntile * 256) * DDIM + kc4 * 64;
        uint32_t dstB = B0 + (uint32_t)(c % NSTAGE) * B_STAGE;
#pragma unroll
        for (int ii = 0; ii < 8; ii++)
            cp16(dstB + bdst[ii], srow + bsrcoff[ii]);
    };

    loadB(0); cp_commit();
    loadB(1); cp_commit();

    // ---- compute-side address precompute ----
    int rowA[4], rswA[4];
#pragma unroll
    for (int mi = 0; mi < 4; mi++) {
        rowA[mi] = warp_m * 64 + mi * 16 + (lane & 7) + ((lane & 8) ? 8 : 0);
        rswA[mi] = rowA[mi] & 7;
    }
    const int khalf = (lane >> 4) & 1;
    const int hhB = (lane >> 3) & 1;
    uint32_t bOff[4]; int bsw[4];
#pragma unroll
    for (int gp = 0; gp < 4; gp++) {
        int gg = 2 * gp + ((lane >> 4) & 1);
        int nB = warp_n * 64 + gg * 8 + (lane & 7);
        bOff[gp] = (uint32_t)(nB * 128);
        bsw[gp] = nB & 7;
    }

    float acc[4][8][4];
    float m[8], s[8];
#pragma unroll
    for (int j = 0; j < 8; j++) { m[j] = __int_as_float(0xff800000); s[j] = 0.f; }
#pragma unroll
    for (int mi = 0; mi < 4; mi++)
#pragma unroll
        for (int g = 0; g < 8; g++)
#pragma unroll
            for (int v = 0; v < 4; v++) acc[mi][g][v] = 0.f;

    for (int c = 0; c < TOT_CHUNK; c++) {
        cp_wait<1>();          // B(c) resident (A included on first iter)
        __syncthreads();

        // prefetch distance 2 into stage (c+2)%3 == (c-1)%3 (freed by barrier)
        if (c + 2 < TOT_CHUNK) loadB(c + 2);
        cp_commit();

        const int sub = c % CHUNKS_PT;
        const int seg = sub >> 2, kc4 = sub & 3;
        const uint32_t Asel = A0 + ((seg == 2) ? 65536u : 0u);
        const uint32_t Bst = B0 + (uint32_t)(c % NSTAGE) * B_STAGE;

#pragma unroll
        for (int ks = 0; ks < 4; ks++) {
            const int k0c = (kc4 * 64 + ks * 16) >> 3;   // even
            uint32_t a[4][4];
#pragma unroll
            for (int mi = 0; mi < 4; mi++) {
                uint32_t ch = (uint32_t)(k0c | khalf);
                ldsm4(a[mi], Asel + (uint32_t)rowA[mi] * 512 +
                              (((ch ^ (uint32_t)rswA[mi])) << 4));
            }
            uint32_t b[8][2];
#pragma unroll
            for (int gp = 0; gp < 4; gp++) {
                uint32_t t4[4];
                uint32_t ch = (uint32_t)(ks * 2 + hhB);
                ldsm4(t4, Bst + bOff[gp] + ((ch ^ (uint32_t)bsw[gp]) << 4));
                b[2 * gp][0] = t4[0]; b[2 * gp][1] = t4[1];
                b[2 * gp + 1][0] = t4[2]; b[2 * gp + 1][1] = t4[3];
            }
#pragma unroll
            for (int mi = 0; mi < 4; mi++)
#pragma unroll
                for (int g = 0; g < 8; g++)
                    mma16816(acc[mi][g], a[mi], b[g]);
        }

        if (sub == CHUNKS_PT - 1) {
            // ---- online softmax update for this 256-col tile ----
#pragma unroll
            for (int mi = 0; mi < 4; mi++) {
#pragma unroll
                for (int p = 0; p < 2; p++) {
                    const int j = mi * 2 + p;
                    float rm = acc[mi][0][2 * p];
#pragma unroll
                    for (int g = 0; g < 8; g++) {
                        rm = fmaxf(rm, acc[mi][g][2 * p]);
                        rm = fmaxf(rm, acc[mi][g][2 * p + 1]);
                    }
                    rm = fmaxf(rm, __shfl_xor_sync(0xffffffffu, rm, 1));
                    rm = fmaxf(rm, __shfl_xor_sync(0xffffffffu, rm, 2));
                    float nm = fmaxf(m[j], rm);
                    float ssum = 0.f;
#pragma unroll
                    for (int g = 0; g < 8; g++) {
                        ssum += ex2f(acc[mi][g][2 * p] - nm);
                        ssum += ex2f(acc[mi][g][2 * p + 1] - nm);
                    }
                    ssum += __shfl_xor_sync(0xffffffffu, ssum, 1);
                    ssum += __shfl_xor_sync(0xffffffffu, ssum, 2);
                    s[j] = s[j] * ex2f(m[j] - nm) + ssum;
                    m[j] = nm;
                }
            }
#pragma unroll
            for (int mi = 0; mi < 4; mi++)
#pragma unroll
                for (int g = 0; g < 8; g++)
#pragma unroll
                    for (int v = 0; v < 4; v++) acc[mi][g][v] = 0.f;
        }
    }

    if ((lane & 3) == 0) {
#pragma unroll
        for (int mi = 0; mi < 4; mi++) {
#pragma unroll
            for (int p = 0; p < 2; p++) {
                const int j = mi * 2 + p;
                int row = rowBase + warp_m * 64 + mi * 16 + (lane >> 2) + 8 * p;
                int slot = blockIdx.x * 4 + warp_n;
                g_m[row * NSLOT + slot] = m[j];
                g_s[row * NSLOT + slot] = s[j];
            }
        }
    }
}

// ---------------------------------------------------------------------
// Kernel 3: combine NSLOT partials per row into the loss.
// ---------------------------------------------------------------------
__global__ void __launch_bounds__(256)
combine_kernel(float* __restrict__ out) {
    int i = blockIdx.x * blockDim.x + threadIdx.x;
    if (i >= N_TOT) return;
    float M = g_m[NSLOT * i];
#pragma unroll
    for (int j = 1; j < NSLOT; j++) M = fmaxf(M, g_m[NSLOT * i + j]);
    float S = 0.f;
#pragma unroll
    for (int j = 0; j < NSLOT; j++)
        S += g_s[NSLOT * i + j] * ex2f(g_m[NSLOT * i + j] - M);
    out[i] = LN2_F * (M + log2f(S)) - INV_T_F * g_diag[i];
}

// ---------------------------------------------------------------------
extern "C" void kernel_launch(void* const* d_in, const int* in_sizes, int n_in,
                              void* d_out, int out_size) {
    const float* Q = (const float*)d_in[0];
    const float* K = (const float*)d_in[1];
    float* out = (float*)d_out;

    cudaFuncSetAttribute(gemm_lse_kernel,
                         cudaFuncAttributeMaxDynamicSharedMemorySize, SMEM_DYN);

    prep_kernel<<<N_TOT, 64>>>(Q, K);
    dim3 g2(C_SPLIT, 64);
    gemm_lse_kernel<<<g2, 256, SMEM_DYN>>>();
    combine_kernel<<<32, 256>>>(out);
}